// round 17
// baseline (speedup 1.0000x reference)
#include <cuda_runtime.h>

// Lifting wavelet v17: SINGLE kernel, half-warp role split.
// Lanes 0-15 (role 0) compute ODD outputs with the 8 wavelet taps; lanes
// 16-31 (role 1) compute EVEN outputs of the SAME 4-pair segments with the
// 8 scaling taps. Each thread loads one 8-float tap vector via a
// role-selected pointer (8 pinned regs instead of 16 — the reg pressure that
// sank v6/v11) and the same 24-float window as its partner lane (duplicate
// half-warp addresses coalesce: L1 wavefronts per byte identical to v3).
// A SEL pass (u[i] = role ? odd : even floats) unifies both roles into one
// FMA chain: no divergence, no extra latency, ~16 live window regs.
// input: (4096, 8192) f32. even = in[:, ::2], odd = in[:, 1::2] (4096 each).
// wavelet[j] = scaling_rec[7-j] * (j odd ? -1 : +1)
// odd_out[k]  = odd[k]  - sum_j wavelet[j] * even[(k-j) mod 4096]
// even_out[k] = even[k] - sum_j scaling[j] * odd[(k-j) mod 4096]
// Output: [even_updated | odd_updated], each 4096x4096 f32.

#define ROWS    4096
#define ROWLEN  8192
#define HALF    4096
#define NTH     256
#define FMASK   (ROWLEN - 1)

__global__ __launch_bounds__(NTH, 6)   // <=42 regs
void wavelet_fwd_v17(const float* __restrict__ in,
                     const float* __restrict__ scaling,
                     const float* __restrict__ scaling_rec,
                     float* __restrict__ out)
{
    const int g    = blockIdx.x * NTH + threadIdx.x;
    const int warp = g >> 5;
    const int lane = threadIdx.x & 31;
    const int role = lane >> 4;          // 0: odd outputs, 1: even outputs
    const int sub  = lane & 15;

    const int row  = warp >> 6;                       // 64 warps per row
    const int pcol = ((warp & 63) << 6) + (sub << 2); // pair base: 0..4092

    const float* rowp = in + (size_t)row * ROWLEN;

    // Taps: one 8-float vector via role-selected pointer (half-warp uniform).
    // Loaded FIRST so the latency overlaps the window loads below.
    const float* tp = role ? scaling : scaling_rec;
    float4 tA = *reinterpret_cast<const float4*>(tp);
    float4 tB = *reinterpret_cast<const float4*>(tp + 4);
    // role 0: t[j] = wavelet[j] = scaling_rec[7-j] * (j odd ? -1 : +1)
    // role 1: t[j] = scaling[j]
    const float t0 = role ? tA.x :  tB.w;
    const float t1 = role ? tA.y : -tB.z;
    const float t2 = role ? tA.z :  tB.y;
    const float t3 = role ? tA.w : -tB.x;
    const float t4 = role ? tB.x :  tA.w;
    const float t5 = role ? tB.y : -tA.z;
    const float t6 = role ? tB.z :  tA.y;
    const float t7 = role ? tB.w : -tA.x;

    // Window: row floats (2*pcol - 16 + i) mod 8192, i = 0..23.
    // 6 aligned float4 loads; both half-warps issue identical addresses, so
    // the warp's wavefront footprint equals a 16-lane load (no L1 growth).
    float wnd[24];
#pragma unroll
    for (int q = 0; q < 6; q++) {
        int fi = (2 * pcol - 16 + 4 * q) & FMASK;
        float4 v = *reinterpret_cast<const float4*>(rowp + fi);
        wnd[4*q+0] = v.x; wnd[4*q+1] = v.y; wnd[4*q+2] = v.z; wnd[4*q+3] = v.w;
    }

    // Role-select the window view (after this, only u/v stay live):
    //   role 0: u[i] = even stream wnd[2i],  v[m] = odd  base wnd[2m+17]
    //   role 1: u[i] = odd  stream wnd[2i+1], v[m] = even base wnd[2m+16]
    float u[12], v[4];
#pragma unroll
    for (int i = 0; i < 12; i++)
        u[i] = role ? wnd[2*i + 1] : wnd[2*i];
#pragma unroll
    for (int m = 0; m < 4; m++)
        v[m] = role ? wnd[2*m + 16] : wnd[2*m + 17];

    // Unified chain: out[m] = v[m] - sum_j t[j] * u[m+8-j].
#pragma unroll
    for (int m = 0; m < 4; m++) {
        v[m] -= t0*u[m+8] + t1*u[m+7] + t2*u[m+6] + t3*u[m+5]
              + t4*u[m+4] + t5*u[m+3] + t6*u[m+2] + t7*u[m+1];
    }

    // role 0 -> odd_updated (second half), role 1 -> even_updated (first half).
    float* dst = out + (size_t)row * HALF + pcol
               + (role ? (size_t)0 : (size_t)ROWS * HALF);
    *reinterpret_cast<float4*>(dst) = make_float4(v[0], v[1], v[2], v[3]);
}

extern "C" void kernel_launch(void* const* d_in, const int* in_sizes, int n_in,
                              void* d_out, int out_size)
{
    const float* input       = (const float*)d_in[0];
    const float* scaling     = (const float*)d_in[1];
    const float* scaling_rec = (const float*)d_in[2];
    float* out = (float*)d_out;

    // warps = ROWS * 64 (each warp: 64 pairs, both roles) -> 8.4M threads.
    const int total_warps = ROWS * 64;
    const int blocks = (total_warps * 32) / NTH;       // 32768
    wavelet_fwd_v17<<<blocks, NTH>>>(input, scaling, scaling_rec, out);
}